// round 15
// baseline (speedup 1.0000x reference)
#include <cuda_runtime.h>

#define BATCH 16
#define ANCH 22743
#define ROW 85
#define NCLS 80
#define NSC (ANCH * NCLS)
#define SCB 8              // scan-role blocks per image
#define CHUNK ((ANCH + SCB - 1) / SCB)   // 2843 anchors per scan block
#define PRE 1000
#define MAXDET 300
#define CONF_THRESH 0.2f
#define PRE_THRESH 0.9f
#define HI_THRESH 0.96f    // bits 0x3F75C28F
#define NMS_THRESH 0.45f
#define MAXK 64
#define SORTN 2048
#define FULLM 0xffffffffu

// fast-path bins over (0.9, 1.0): (bits - bits(0.9f)) >> 11, 1024 bins
#define B9OFF 0x3F666666u
#define NBF 1024
#define HBIN 492           // bin >= HBIN  =>  bits >= 0x3F75C666 > bits(0.96f)
#define HCAP 4096          // high-list capacity (mean ~1475, ~68 sigma)
// slow-path histogram over (0.2, 1.0): (bits - 0x3E000000) >> 12
#define NBS 6144
#define B2OFF 0x3E000000u
#define GRPS 6             // NBS / 1024

// ---------------- device scratch (static; no allocations) ----------------
__device__ unsigned long long g_hkey[BATCH][HCAP];   // dense s>0.96 tier
__device__ float4 g_hbox[BATCH][HCAP];
__device__ int g_hcnt[BATCH];
__device__ int g_hist[BATCH][NBF];   // zero at load; tail re-zeroes each run
__device__ int g_done[BATCH];        // scan-block completion counters

struct SMF {
    unsigned long long keys[SORTN];   // bin-grouped candidates >= cutoff
    int aux[SORTN];                   // high-list slot (fast) / flat (slow)
    int histF[NBF];                   // fast bin counts (1 per thread)
    int bposF[NBF];                   // fast bin base, then scatter cursor
    int histS[NBS];                   // slow-path histogram
    int bposS[NBS];
    int rsum[1024];                   // suffix sums (shared fast/slow)
    int wred[33];
    int wcnt[32 * NCLS];
    int wof[32 * NCLS];
    int ccnt[NCLS];
    float rbx1[1024], rby1[1024], rbx2[1024], rby2[1024];
    float sx1[1024], sy1[1024], sx2[1024], sy2[1024], sar[1024];
    float ssc[1024];
    int slb[1024];
    int clist[NCLS * MAXK];
    int keepf[1024];
    int wscan[33];
    int n_high, cstar, mcnt, smax;
};

__device__ __forceinline__ int bucket_fast(unsigned sb) {
    return min((int)((sb - B9OFF) >> 11), NBF - 1);
}
__device__ __forceinline__ int bucket_slow(unsigned sb) {
    return min((int)((sb - B2OFF) >> 12), NBS - 1);
}

// Inclusive suffix sums of per-thread value v -> sm.rsum (block-wide)
__device__ __forceinline__ void suffix_scan(SMF& sm, int v, int tid,
                                            int lane, int wid) {
    int vs = v;
#pragma unroll
    for (int off = 1; off < 32; off <<= 1) {
        int t = __shfl_down_sync(FULLM, vs, off);
        if (lane + off < 32) vs += t;
    }
    if (lane == 0) sm.wred[wid] = vs;
    __syncthreads();
    if (wid == 0) {
        int w = sm.wred[lane];
        __syncwarp();
#pragma unroll
        for (int off = 1; off < 32; off <<= 1) {
            int t = __shfl_down_sync(FULLM, w, off);
            if (lane + off < 32) w += t;
        }
        sm.wred[lane] = w;  // inclusive suffix over warp totals
    }
    __syncthreads();
    sm.rsum[tid] = vs + ((wid < 31) ? sm.wred[wid + 1] : 0);
    __syncthreads();
}

// Single kernel: blocks (0..SCB-1, b) scan; block (SCB, b) runs the tail.
// All 144 blocks are co-resident (1 block/SM via smem) -> spin-wait is safe.
__global__ void __launch_bounds__(1024, 1)
yolo_kernel(const float* __restrict__ preds, float* __restrict__ out) {
    extern __shared__ char smc[];
    SMF& sm = *(SMF*)smc;
    int b = blockIdx.y;
    int tid = threadIdx.x;
    int lane = tid & 31;
    int wid = tid >> 5;

    if (blockIdx.x < SCB) {
        // ================= scan role =================
        int astart = blockIdx.x * CHUNK;
        int aend = min(astart + CHUNK, ANCH);
        const int ITERS = (CHUNK + 1023) / 1024;
#pragma unroll
        for (int it = 0; it < ITERS; it++) {
            int a0 = astart + it * 1024 + tid;
            bool inb = a0 < aend;
            float conf0 =
                inb ? preds[((size_t)b * ANCH + a0) * ROW + 4] : 0.0f;
            unsigned m = __ballot_sync(FULLM, inb && (conf0 > PRE_THRESH));
            while (m) {
                int src = __ffs(m) - 1;
                m &= m - 1;
                int a = __shfl_sync(FULLM, a0, src);
                float conf = __shfl_sync(FULLM, conf0, src);
                const float* row = preds + ((size_t)b * ANCH + a) * ROW;
                float b0 = row[0], b1 = row[1], b2 = row[2], b3 = row[3];
#pragma unroll
                for (int part = 0; part < 3; part++) {
                    int k = part * 32 + lane;
                    float p = (k < NCLS) ? row[5 + k] : 0.0f;
                    float s = __fmul_rn(p, conf);
                    if (k < NCLS && s > PRE_THRESH) {
                        unsigned sb = __float_as_uint(s);
                        atomicAdd(&g_hist[b][bucket_fast(sb)], 1);
                        if (s > HI_THRESH) {
                            int hp = atomicAdd(&g_hcnt[b], 1);
                            if (hp < HCAP) {
                                unsigned flat =
                                    (unsigned)a * 80u + (unsigned)k;
                                g_hkey[b][hp] =
                                    ((unsigned long long)sb << 32) |
                                    (unsigned long long)(~flat);
                                g_hbox[b][hp] =
                                    make_float4(b0, b1, b2, b3);
                            }
                        }
                    }
                }
            }
        }
        __threadfence();
        __syncthreads();
        if (tid == 0) atomicAdd(&g_done[b], 1);
        return;
    }

    // ================= tail role =================
    // ---- dependency-free init (overlaps scan) ----
    sm.ssc[tid] = -1.0f;    // matches reference semantics for empty slots
    sm.slb[tid] = 0;
    for (int i = tid; i < 32 * NCLS; i += 1024) sm.wcnt[i] = 0;
    sm.keepf[tid] = 0;
    if (tid == 0) { sm.cstar = NBF; sm.mcnt = 0; sm.smax = 0; }

    // ---- wait for this image's scan blocks ----
    if (tid == 0) {
        while (atomicAdd(&g_done[b], 0) < SCB) {}
        g_done[b] = 0;
        __threadfence();
    }
    __syncthreads();

    int v = g_hist[b][tid];   // exactly one fast bin per thread
    sm.histF[tid] = v;
    g_hist[b][tid] = 0;
    if (tid == 0) {
        sm.n_high = g_hcnt[b];
        g_hcnt[b] = 0;
    }
    __syncthreads();

    // ---- suffix over 1024 bins, cutoff, bases ----
    suffix_scan(sm, v, tid, lane, wid);
    if (sm.rsum[tid] >= PRE && (tid == 1023 || sm.rsum[tid + 1] < PRE)) {
        sm.cstar = tid;
        sm.mcnt = sm.rsum[tid];
    }
    sm.bposF[tid] = (tid < 1023) ? sm.rsum[tid + 1] : 0;  // bin base
    __syncthreads();

    bool slow = (sm.rsum[0] < PRE) || (sm.cstar < HBIN) ||
                (sm.n_high > HCAP);

    if (!slow) {
        int cs = sm.cstar;
        int nh = sm.n_high;

        // ---- compact dense high tier into bin regions ----
        for (int i = tid; i < nh; i += 1024) {
            unsigned long long key = g_hkey[b][i];
            int bk = bucket_fast((unsigned)(key >> 32));
            if (bk >= cs) {
                int pos = atomicAdd(&sm.bposF[bk], 1);
                if (pos < SORTN) {
                    sm.keys[pos] = key;
                    sm.aux[pos] = i;
                }
            }
        }
        __syncthreads();

        // ---- exact rank; write score/label/box at rank directly ----
        unsigned lmxb = 0;
        int mC = min(sm.mcnt, SORTN);
#pragma unroll
        for (int it = 0; it < 2; it++) {
            int idx = tid + it * 1024;
            if (idx < mC) {
                unsigned long long key = sm.keys[idx];
                int bk = bucket_fast((unsigned)(key >> 32));
                int endv = sm.bposF[bk];
                int base = endv - sm.histF[bk];
                int end = min(endv, SORTN);
                int rank = base;
                for (int j = base; j < end; j++)
                    rank += (sm.keys[j] > key);
                if (rank < PRE) {
                    unsigned flat = ~((unsigned)(key & 0xffffffffull));
                    sm.ssc[rank] = __uint_as_float((unsigned)(key >> 32));
                    sm.slb[rank] = (int)(flat - (flat / 80u) * 80u);
                    float4 bx = g_hbox[b][sm.aux[idx]];
                    sm.rbx1[rank] = bx.x; sm.rby1[rank] = bx.y;
                    sm.rbx2[rank] = bx.z; sm.rby2[rank] = bx.w;
                    float mx = fmaxf(fmaxf(bx.x, bx.y), fmaxf(bx.z, bx.w));
                    lmxb = max(lmxb, (unsigned)__float_as_int(mx));
                }
            }
        }
#pragma unroll
        for (int off = 16; off > 0; off >>= 1)
            lmxb = max(lmxb, __shfl_xor_sync(FULLM, lmxb, off));
        if (lane == 0) atomicMax(&sm.smax, (int)lmxb);
        __syncthreads();
    } else {
        // ======= slow path (exactness-gated; statistically never) ========
#pragma unroll
        for (int q = 0; q < GRPS; q++) sm.histS[tid * GRPS + q] = 0;
        if (tid == 0) { sm.cstar = NBS; sm.mcnt = 0; }
        __syncthreads();
        const float* bp = preds + (size_t)b * ANCH * ROW;
        for (int i = tid; i < NSC; i += 1024) {
            int a = i / 80, k = i - a * 80;
            float s = __fmul_rn(bp[(size_t)a * ROW + 5 + k],
                                bp[(size_t)a * ROW + 4]);
            if (s > CONF_THRESH)
                atomicAdd(&sm.histS[bucket_slow(__float_as_uint(s))], 1);
        }
        __syncthreads();
        {
            int vs = 0;
#pragma unroll
            for (int q = 0; q < GRPS; q++) vs += sm.histS[tid * GRPS + q];
            suffix_scan(sm, vs, tid, lane, wid);
        }
        int t_target = min(PRE, sm.rsum[0]);
        if (t_target > 0 && sm.rsum[tid] >= t_target &&
            (tid == 1023 || sm.rsum[tid + 1] < t_target)) {
            int acc = (tid < 1023) ? sm.rsum[tid + 1] : 0;
            for (int bk = tid * GRPS + GRPS - 1; bk >= tid * GRPS; bk--) {
                acc += sm.histS[bk];
                if (acc >= t_target) {
                    sm.cstar = bk;
                    sm.mcnt = acc;
                    break;
                }
            }
        }
        {
            int run = (tid < 1023) ? sm.rsum[tid + 1] : 0;
            for (int q = GRPS - 1; q >= 0; q--) {
                sm.bposS[tid * GRPS + q] = run;
                run += sm.histS[tid * GRPS + q];
            }
        }
        __syncthreads();
        int cs = sm.cstar;
        for (int i = tid; i < NSC; i += 1024) {
            int a = i / 80, k = i - a * 80;
            float s = __fmul_rn(bp[(size_t)a * ROW + 5 + k],
                                bp[(size_t)a * ROW + 4]);
            if (s > CONF_THRESH) {
                int bk = bucket_slow(__float_as_uint(s));
                if (bk >= cs) {
                    int pos = atomicAdd(&sm.bposS[bk], 1);
                    if (pos < SORTN) {
                        sm.keys[pos] =
                            ((unsigned long long)__float_as_uint(s) << 32) |
                            (unsigned long long)(~(unsigned)i);
                        sm.aux[pos] = i;
                    }
                }
            }
        }
        __syncthreads();
        int mC = min(sm.mcnt, SORTN);
#pragma unroll
        for (int it = 0; it < 2; it++) {
            int idx = tid + it * 1024;
            if (idx < mC) {
                unsigned long long key = sm.keys[idx];
                int bk = bucket_slow((unsigned)(key >> 32));
                int endv = sm.bposS[bk];
                int base = endv - sm.histS[bk];
                int end = min(endv, SORTN);
                int rank = base;
                for (int j = base; j < end; j++)
                    rank += (sm.keys[j] > key);
                if (rank < PRE) {
                    unsigned flat = (unsigned)sm.aux[idx];
                    sm.ssc[rank] = __uint_as_float((unsigned)(key >> 32));
                    sm.slb[rank] = (int)(flat - (flat / 80u) * 80u);
                    const float* row = bp + (size_t)(flat / 80u) * ROW;
                    float b0 = row[0], b1 = row[1];
                    float b2 = row[2], b3 = row[3];
                    sm.rbx1[rank] = b0; sm.rby1[rank] = b1;
                    sm.rbx2[rank] = b2; sm.rby2[rank] = b3;
                    float mx = fmaxf(fmaxf(b0, b1), fmaxf(b2, b3));
                    atomicMax(&sm.smax, __float_as_int(mx));
                }
            }
        }
        __syncthreads();
    }

    // ---- class shift (bit-exact reference arithmetic) ----
    {
        float M = __int_as_float(sm.smax);
        float shb = __fadd_rn(M, 1.0f);
        float sh = __fmul_rn((float)sm.slb[tid], shb);
        float x1 = __fadd_rn(sm.rbx1[tid], sh);
        float y1 = __fadd_rn(sm.rby1[tid], sh);
        float x2 = __fadd_rn(sm.rbx2[tid], sh);
        float y2 = __fadd_rn(sm.rby2[tid], sh);
        sm.sx1[tid] = x1; sm.sy1[tid] = y1; sm.sx2[tid] = x2; sm.sy2[tid] = y2;
        sm.sar[tid] = __fmul_rn(fmaxf(__fsub_rn(x2, x1), 0.0f),
                                fmaxf(__fsub_rn(y2, y1), 0.0f));
    }

    // ---- stable per-class grouping: match_any + cross-warp shfl scan ----
    int mylbl = (tid < PRE) ? sm.slb[tid] : -1;
    unsigned grpm = __match_any_sync(FULLM, mylbl);
    int wrank = __popc(grpm & ((1u << lane) - 1u));
    if (tid < PRE && wrank == 0)
        sm.wcnt[wid * NCLS + mylbl] = __popc(grpm);
    __syncthreads();
    for (int c = wid; c < NCLS; c += 32) {
        int vv = sm.wcnt[lane * NCLS + c];
        int x = vv;
#pragma unroll
        for (int off = 1; off < 32; off <<= 1) {
            int t = __shfl_up_sync(FULLM, x, off);
            if (lane >= off) x += t;
        }
        sm.wof[lane * NCLS + c] = x - vv;  // exclusive
        if (lane == 31) sm.ccnt[c] = x;
    }
    __syncthreads();
    if (tid < PRE) {
        int pos = sm.wof[wid * NCLS + mylbl] + wrank;
        if (pos < MAXK) sm.clist[mylbl * MAXK + pos] = tid;
    }
    __syncthreads();

    // ---- warp-parallel per-class greedy NMS (one warp per class) ----
    for (int c = wid; c < NCLS; c += 32) {
        int kc = min(sm.ccnt[c], MAXK);
        if (kc == 0) continue;
        if (kc <= 32) {
            int j1 = (lane < kc) ? sm.clist[c * MAXK + lane] : 0;
            float x1a = sm.sx1[j1], y1a = sm.sy1[j1];
            float x2a = sm.sx2[j1], y2a = sm.sy2[j1], ara = sm.sar[j1];
            unsigned keep =
                __ballot_sync(FULLM, lane < kc && sm.ssc[j1] > CONF_THRESH);
            for (int ii = 0; ii < kc; ii++) {
                if (!((keep >> ii) & 1u)) continue;  // warp-uniform
                float px1 = __shfl_sync(FULLM, x1a, ii);
                float py1 = __shfl_sync(FULLM, y1a, ii);
                float px2 = __shfl_sync(FULLM, x2a, ii);
                float py2 = __shfl_sync(FULLM, y2a, ii);
                float par = __shfl_sync(FULLM, ara, ii);
                float iw = fmaxf(__fsub_rn(fminf(px2, x2a), fmaxf(px1, x1a)), 0.0f);
                float ih = fmaxf(__fsub_rn(fminf(py2, y2a), fmaxf(py1, y1a)), 0.0f);
                float inter = __fmul_rn(iw, ih);
                float den = __fadd_rn(__fsub_rn(__fadd_rn(par, ara), inter), 1e-7f);
                bool s1 = (lane > ii) && (lane < kc) &&
                          (__fdiv_rn(inter, den) > NMS_THRESH);
                keep &= ~__ballot_sync(FULLM, s1);
            }
            if (lane < kc) sm.keepf[j1] = (int)((keep >> lane) & 1u);
        } else {
            int i1 = lane, i2 = lane + 32;
            int j1 = sm.clist[c * MAXK + i1];
            int j2 = (i2 < kc) ? sm.clist[c * MAXK + i2] : 0;
            float x1a = sm.sx1[j1], y1a = sm.sy1[j1];
            float x2a = sm.sx2[j1], y2a = sm.sy2[j1], ara = sm.sar[j1];
            float x1b = sm.sx1[j2], y1b = sm.sy1[j2];
            float x2b = sm.sx2[j2], y2b = sm.sy2[j2], arb = sm.sar[j2];
            unsigned m1 = __ballot_sync(FULLM, sm.ssc[j1] > CONF_THRESH);
            unsigned m2 =
                __ballot_sync(FULLM, i2 < kc && sm.ssc[j2] > CONF_THRESH);
            unsigned long long keep =
                (unsigned long long)m1 | ((unsigned long long)m2 << 32);
            for (int ii = 0; ii < kc; ii++) {
                if (!((keep >> ii) & 1ull)) continue;
                int src = ii & 31;
                bool hi = ii >= 32;
                float px1 = __shfl_sync(FULLM, hi ? x1b : x1a, src);
                float py1 = __shfl_sync(FULLM, hi ? y1b : y1a, src);
                float px2 = __shfl_sync(FULLM, hi ? x2b : x2a, src);
                float py2 = __shfl_sync(FULLM, hi ? y2b : y2a, src);
                float par = __shfl_sync(FULLM, hi ? arb : ara, src);
                float iw1 = fmaxf(__fsub_rn(fminf(px2, x2a), fmaxf(px1, x1a)), 0.0f);
                float ih1 = fmaxf(__fsub_rn(fminf(py2, y2a), fmaxf(py1, y1a)), 0.0f);
                float it1 = __fmul_rn(iw1, ih1);
                float dn1 = __fadd_rn(__fsub_rn(__fadd_rn(par, ara), it1), 1e-7f);
                bool s1 = (i1 > ii) && (__fdiv_rn(it1, dn1) > NMS_THRESH);
                float iw2 = fmaxf(__fsub_rn(fminf(px2, x2b), fmaxf(px1, x1b)), 0.0f);
                float ih2 = fmaxf(__fsub_rn(fminf(py2, y2b), fmaxf(py1, y1b)), 0.0f);
                float it2 = __fmul_rn(iw2, ih2);
                float dn2 = __fadd_rn(__fsub_rn(__fadd_rn(par, arb), it2), 1e-7f);
                bool s2 = (i2 > ii) && (i2 < kc) &&
                          (__fdiv_rn(it2, dn2) > NMS_THRESH);
                unsigned b1 = __ballot_sync(FULLM, s1);
                unsigned b2 = __ballot_sync(FULLM, s2);
                keep &= ~((unsigned long long)b1 |
                          ((unsigned long long)b2 << 32));
            }
            sm.keepf[j1] = (int)((keep >> i1) & 1ull);
            if (i2 < kc) sm.keepf[j2] = (int)((keep >> i2) & 1ull);
        }
    }
    __syncthreads();

    // ---- keep-flag prefix sum (warp shuffles) ----
    int myscan, total;
    {
        int p = sm.keepf[tid];
#pragma unroll
        for (int off = 1; off < 32; off <<= 1) {
            int t = __shfl_up_sync(FULLM, p, off);
            if (lane >= off) p += t;
        }
        if (lane == 31) sm.wscan[wid] = p;
        __syncthreads();
        if (wid == 0) {
            int w = sm.wscan[lane];
            __syncwarp();
#pragma unroll
            for (int off = 1; off < 32; off <<= 1) {
                int t = __shfl_up_sync(FULLM, w, off);
                if (lane >= off) w += t;
            }
            sm.wscan[lane] = w;
        }
        __syncthreads();
        int base = (wid > 0) ? sm.wscan[wid - 1] : 0;
        myscan = base + p;
        total = sm.wscan[31];
    }

    // ---- emit top-300 ----
    float* ob = out;                               // [16][300][4]
    float* os = out + (size_t)BATCH * MAXDET * 4;  // [16][300]
    float* ol = out + (size_t)BATCH * MAXDET * 5;  // [16][300] labels as f32

    if (tid < PRE && sm.keepf[tid]) {
        int m = myscan - 1;
        if (m < MAXDET) {
            float* p = ob + ((size_t)b * MAXDET + m) * 4;
            p[0] = sm.rbx1[tid]; p[1] = sm.rby1[tid];
            p[2] = sm.rbx2[tid]; p[3] = sm.rby2[tid];
            os[b * MAXDET + m] = sm.ssc[tid];
            ol[b * MAXDET + m] = (float)sm.slb[tid];
        }
    }
    for (int m = tid; m < MAXDET; m += 1024) {
        if (m >= total) {
            float* p = ob + ((size_t)b * MAXDET + m) * 4;
            p[0] = 0.0f; p[1] = 0.0f; p[2] = 0.0f; p[3] = 0.0f;
            os[b * MAXDET + m] = 0.0f;
            ol[b * MAXDET + m] = -1.0f;
        }
    }
}

extern "C" void kernel_launch(void* const* d_in, const int* in_sizes, int n_in,
                              void* d_out, int out_size) {
    (void)in_sizes; (void)n_in; (void)out_size;
    const float* preds = (const float*)d_in[0];
    float* out = (float*)d_out;

    cudaFuncSetAttribute(yolo_kernel,
                         cudaFuncAttributeMaxDynamicSharedMemorySize,
                         (int)sizeof(SMF));

    yolo_kernel<<<dim3(SCB + 1, BATCH), 1024, sizeof(SMF)>>>(preds, out);
}

// round 16
// speedup vs baseline: 1.0860x; 1.0860x over previous
#include <cuda_runtime.h>

#define BATCH 16
#define ANCH 22743
#define ROW 85
#define NCLS 80
#define NSC (ANCH * NCLS)
#define ABLK 89            // ceil(ANCH / 256)
#define PRE 1000
#define MAXDET 300
#define CONF_THRESH 0.2f
#define PRE_THRESH 0.9f
#define HI_THRESH 0.96f    // bits 0x3F75C28F
#define NMS_THRESH 0.45f
#define MAXK 64
#define SORTN 2048
#define FULLM 0xffffffffu

// fast-path bins over (0.9, 1.0): (bits - bits(0.9f)) >> 11, 1024 bins
#define B9OFF 0x3F666666u
#define NBF 1024
#define HBIN 492           // bin >= HBIN  =>  bits >= 0x3F75C666 > bits(0.96f)
#define HCAP 4096          // high-list capacity (mean ~1475, ~68 sigma)
// slow-path histogram over (0.2, 1.0): (bits - 0x3E000000) >> 12
#define NBS 6144
#define B2OFF 0x3E000000u
#define GRPS 6             // NBS / 1024

// ---------------- device scratch (static; no allocations) ----------------
__device__ unsigned long long g_hkey[BATCH][HCAP];   // dense s>0.96 tier
__device__ float4 g_hbox[BATCH][HCAP];
__device__ int g_hcnt[BATCH];
__device__ int g_hist[BATCH][NBF];   // zero at load; final re-zeroes each run

struct SMF {
    unsigned long long keys[SORTN];   // bin-grouped candidates >= cutoff
    float4 kbox[SORTN];               // boxes staged alongside keys
    int histF[NBF];                   // fast bin counts (1 per thread)
    int bposF[NBF];                   // fast bin base, then scatter cursor
    int histS[NBS];                   // slow-path histogram
    int bposS[NBS];
    int rsum[1024];                   // suffix sums (shared fast/slow)
    int wred[33];
    int wcnt[32 * NCLS];
    int wof[32 * NCLS];
    int ccnt[NCLS];
    float rbx1[1024], rby1[1024], rbx2[1024], rby2[1024];
    float sx1[1024], sy1[1024], sx2[1024], sy2[1024], sar[1024];
    float ssc[1024];
    int slb[1024];
    int clist[NCLS * MAXK];
    int keepf[1024];
    int wscan[33];
    int n_high, cstar, mcnt, smax;
};

__device__ __forceinline__ int bucket_fast(unsigned sb) {
    return min((int)((sb - B9OFF) >> 11), NBF - 1);
}
__device__ __forceinline__ int bucket_slow(unsigned sb) {
    return min((int)((sb - B2OFF) >> 12), NBS - 1);
}

// Scan: conf>0.9 prefilter, warp-cooperative scoring. Emits only the fast-bin
// histogram (all s>0.9) and the dense high tier (s>0.96). No block syncs.
__global__ void scan_kernel(const float* __restrict__ preds) {
    cudaTriggerProgrammaticLaunchCompletion();
    int b = blockIdx.y;
    int a0 = blockIdx.x * 256 + threadIdx.x;
    int lane = threadIdx.x & 31;
    bool inb = a0 < ANCH;
    float conf0 = inb ? preds[((size_t)b * ANCH + a0) * ROW + 4] : 0.0f;
    unsigned m = __ballot_sync(FULLM, inb && (conf0 > PRE_THRESH));
    while (m) {
        int src = __ffs(m) - 1;
        m &= m - 1;
        int a = __shfl_sync(FULLM, a0, src);
        float conf = __shfl_sync(FULLM, conf0, src);
        const float* row = preds + ((size_t)b * ANCH + a) * ROW;
        float b0 = row[0], b1 = row[1], b2 = row[2], b3 = row[3];
#pragma unroll
        for (int part = 0; part < 3; part++) {
            int k = part * 32 + lane;
            float p = (k < NCLS) ? row[5 + k] : 0.0f;
            float s = __fmul_rn(p, conf);
            if (k < NCLS && s > PRE_THRESH) {
                unsigned sb = __float_as_uint(s);
                atomicAdd(&g_hist[b][bucket_fast(sb)], 1);
                if (s > HI_THRESH) {
                    int hp = atomicAdd(&g_hcnt[b], 1);
                    if (hp < HCAP) {
                        unsigned flat = (unsigned)a * 80u + (unsigned)k;
                        g_hkey[b][hp] =
                            ((unsigned long long)sb << 32) |
                            (unsigned long long)(~flat);
                        g_hbox[b][hp] = make_float4(b0, b1, b2, b3);
                    }
                }
            }
        }
    }
}

// Inclusive suffix sums of per-thread value v -> sm.rsum (block-wide)
__device__ __forceinline__ void suffix_scan(SMF& sm, int v, int tid,
                                            int lane, int wid) {
    int vs = v;
#pragma unroll
    for (int off = 1; off < 32; off <<= 1) {
        int t = __shfl_down_sync(FULLM, vs, off);
        if (lane + off < 32) vs += t;
    }
    if (lane == 0) sm.wred[wid] = vs;
    __syncthreads();
    if (wid == 0) {
        int w = sm.wred[lane];
        __syncwarp();
#pragma unroll
        for (int off = 1; off < 32; off <<= 1) {
            int t = __shfl_down_sync(FULLM, w, off);
            if (lane + off < 32) w += t;
        }
        sm.wred[lane] = w;  // inclusive suffix over warp totals
    }
    __syncthreads();
    sm.rsum[tid] = vs + ((wid < 31) ? sm.wred[wid + 1] : 0);
    __syncthreads();
}

__global__ void __launch_bounds__(1024, 1)
final_kernel(const float* __restrict__ preds, float* __restrict__ out) {
    extern __shared__ char smc[];
    SMF& sm = *(SMF*)smc;
    int b = blockIdx.x;
    int tid = threadIdx.x;
    int lane = tid & 31;
    int wid = tid >> 5;

    // ---- dependency-free init ----
    sm.ssc[tid] = -1.0f;    // matches reference semantics for empty slots
    sm.slb[tid] = 0;
    for (int i = tid; i < 32 * NCLS; i += 1024) sm.wcnt[i] = 0;
    sm.keepf[tid] = 0;
    if (tid == 0) { sm.cstar = NBF; sm.mcnt = 0; sm.smax = 0; }

    // ---- wait for scan_kernel's writes, then ingest ----
    cudaGridDependencySynchronize();
    int v = g_hist[b][tid];   // exactly one fast bin per thread
    sm.histF[tid] = v;
    g_hist[b][tid] = 0;
    if (tid == 0) {
        sm.n_high = g_hcnt[b];
        g_hcnt[b] = 0;
    }
    __syncthreads();

    // ---- suffix over 1024 bins, cutoff, bases ----
    suffix_scan(sm, v, tid, lane, wid);
    if (sm.rsum[tid] >= PRE && (tid == 1023 || sm.rsum[tid + 1] < PRE)) {
        sm.cstar = tid;
        sm.mcnt = sm.rsum[tid];
    }
    sm.bposF[tid] = (tid < 1023) ? sm.rsum[tid + 1] : 0;  // bin base
    __syncthreads();

    bool slow = (sm.rsum[0] < PRE) || (sm.cstar < HBIN) ||
                (sm.n_high > HCAP);

    if (!slow) {
        int cs = sm.cstar;
        int nh = sm.n_high;

        // ---- compact dense high tier into bin regions (boxes staged) ----
        for (int i = tid; i < nh; i += 1024) {
            unsigned long long key = g_hkey[b][i];
            int bk = bucket_fast((unsigned)(key >> 32));
            if (bk >= cs) {
                int pos = atomicAdd(&sm.bposF[bk], 1);
                if (pos < SORTN) {
                    sm.keys[pos] = key;
                    sm.kbox[pos] = g_hbox[b][i];   // coalesced here
                }
            }
        }
        __syncthreads();

        // ---- exact rank; write score/label/box at rank directly ----
        unsigned lmxb = 0;
        int mC = min(sm.mcnt, SORTN);
#pragma unroll
        for (int it = 0; it < 2; it++) {
            int idx = tid + it * 1024;
            if (idx < mC) {
                unsigned long long key = sm.keys[idx];
                int bk = bucket_fast((unsigned)(key >> 32));
                int endv = sm.bposF[bk];
                int base = endv - sm.histF[bk];
                int end = min(endv, SORTN);
                int rank = base;
                for (int j = base; j < end; j++)
                    rank += (sm.keys[j] > key);
                if (rank < PRE) {
                    unsigned flat = ~((unsigned)(key & 0xffffffffull));
                    sm.ssc[rank] = __uint_as_float((unsigned)(key >> 32));
                    sm.slb[rank] = (int)(flat - (flat / 80u) * 80u);
                    float4 bx = sm.kbox[idx];      // LDS, not scattered LDG
                    sm.rbx1[rank] = bx.x; sm.rby1[rank] = bx.y;
                    sm.rbx2[rank] = bx.z; sm.rby2[rank] = bx.w;
                    float mx = fmaxf(fmaxf(bx.x, bx.y), fmaxf(bx.z, bx.w));
                    lmxb = max(lmxb, (unsigned)__float_as_int(mx));
                }
            }
        }
#pragma unroll
        for (int off = 16; off > 0; off >>= 1)
            lmxb = max(lmxb, __shfl_xor_sync(FULLM, lmxb, off));
        if (lane == 0) atomicMax(&sm.smax, (int)lmxb);
        __syncthreads();
    } else {
        // ======= slow path (exactness-gated; statistically never) ========
#pragma unroll
        for (int q = 0; q < GRPS; q++) sm.histS[tid * GRPS + q] = 0;
        if (tid == 0) { sm.cstar = NBS; sm.mcnt = 0; }
        __syncthreads();
        const float* bp = preds + (size_t)b * ANCH * ROW;
        for (int i = tid; i < NSC; i += 1024) {
            int a = i / 80, k = i - a * 80;
            float s = __fmul_rn(bp[(size_t)a * ROW + 5 + k],
                                bp[(size_t)a * ROW + 4]);
            if (s > CONF_THRESH)
                atomicAdd(&sm.histS[bucket_slow(__float_as_uint(s))], 1);
        }
        __syncthreads();
        {
            int vs = 0;
#pragma unroll
            for (int q = 0; q < GRPS; q++) vs += sm.histS[tid * GRPS + q];
            suffix_scan(sm, vs, tid, lane, wid);
        }
        int t_target = min(PRE, sm.rsum[0]);
        if (t_target > 0 && sm.rsum[tid] >= t_target &&
            (tid == 1023 || sm.rsum[tid + 1] < t_target)) {
            int acc = (tid < 1023) ? sm.rsum[tid + 1] : 0;
            for (int bk = tid * GRPS + GRPS - 1; bk >= tid * GRPS; bk--) {
                acc += sm.histS[bk];
                if (acc >= t_target) {
                    sm.cstar = bk;
                    sm.mcnt = acc;
                    break;
                }
            }
        }
        {
            int run = (tid < 1023) ? sm.rsum[tid + 1] : 0;
            for (int q = GRPS - 1; q >= 0; q--) {
                sm.bposS[tid * GRPS + q] = run;
                run += sm.histS[tid * GRPS + q];
            }
        }
        __syncthreads();
        int cs = sm.cstar;
        for (int i = tid; i < NSC; i += 1024) {
            int a = i / 80, k = i - a * 80;
            float s = __fmul_rn(bp[(size_t)a * ROW + 5 + k],
                                bp[(size_t)a * ROW + 4]);
            if (s > CONF_THRESH) {
                int bk = bucket_slow(__float_as_uint(s));
                if (bk >= cs) {
                    int pos = atomicAdd(&sm.bposS[bk], 1);
                    if (pos < SORTN) {
                        sm.keys[pos] =
                            ((unsigned long long)__float_as_uint(s) << 32) |
                            (unsigned long long)(~(unsigned)i);
                        const float* row = bp + (size_t)a * ROW;
                        sm.kbox[pos] =
                            make_float4(row[0], row[1], row[2], row[3]);
                    }
                }
            }
        }
        __syncthreads();
        int mC = min(sm.mcnt, SORTN);
#pragma unroll
        for (int it = 0; it < 2; it++) {
            int idx = tid + it * 1024;
            if (idx < mC) {
                unsigned long long key = sm.keys[idx];
                int bk = bucket_slow((unsigned)(key >> 32));
                int endv = sm.bposS[bk];
                int base = endv - sm.histS[bk];
                int end = min(endv, SORTN);
                int rank = base;
                for (int j = base; j < end; j++)
                    rank += (sm.keys[j] > key);
                if (rank < PRE) {
                    unsigned flat = ~((unsigned)(key & 0xffffffffull));
                    sm.ssc[rank] = __uint_as_float((unsigned)(key >> 32));
                    sm.slb[rank] = (int)(flat - (flat / 80u) * 80u);
                    float4 bx = sm.kbox[idx];
                    sm.rbx1[rank] = bx.x; sm.rby1[rank] = bx.y;
                    sm.rbx2[rank] = bx.z; sm.rby2[rank] = bx.w;
                    float mx = fmaxf(fmaxf(bx.x, bx.y), fmaxf(bx.z, bx.w));
                    atomicMax(&sm.smax, __float_as_int(mx));
                }
            }
        }
        __syncthreads();
        // ranks >= mcnt keep init values: ssc=-1, slb=0 (matches reference)
    }

    // ---- class shift (bit-exact reference arithmetic) ----
    {
        float M = __int_as_float(sm.smax);
        float shb = __fadd_rn(M, 1.0f);
        float sh = __fmul_rn((float)sm.slb[tid], shb);
        float x1 = __fadd_rn(sm.rbx1[tid], sh);
        float y1 = __fadd_rn(sm.rby1[tid], sh);
        float x2 = __fadd_rn(sm.rbx2[tid], sh);
        float y2 = __fadd_rn(sm.rby2[tid], sh);
        sm.sx1[tid] = x1; sm.sy1[tid] = y1; sm.sx2[tid] = x2; sm.sy2[tid] = y2;
        sm.sar[tid] = __fmul_rn(fmaxf(__fsub_rn(x2, x1), 0.0f),
                                fmaxf(__fsub_rn(y2, y1), 0.0f));
    }

    // ---- stable per-class grouping: match_any + cross-warp shfl scan ----
    int mylbl = (tid < PRE) ? sm.slb[tid] : -1;
    unsigned grpm = __match_any_sync(FULLM, mylbl);
    int wrank = __popc(grpm & ((1u << lane) - 1u));
    if (tid < PRE && wrank == 0)
        sm.wcnt[wid * NCLS + mylbl] = __popc(grpm);
    __syncthreads();
    for (int c = wid; c < NCLS; c += 32) {
        int vv = sm.wcnt[lane * NCLS + c];
        int x = vv;
#pragma unroll
        for (int off = 1; off < 32; off <<= 1) {
            int t = __shfl_up_sync(FULLM, x, off);
            if (lane >= off) x += t;
        }
        sm.wof[lane * NCLS + c] = x - vv;  // exclusive
        if (lane == 31) sm.ccnt[c] = x;
    }
    __syncthreads();
    if (tid < PRE) {
        int pos = sm.wof[wid * NCLS + mylbl] + wrank;
        if (pos < MAXK) sm.clist[mylbl * MAXK + pos] = tid;
    }
    __syncthreads();

    // ---- warp-parallel per-class greedy NMS (one warp per class) ----
    for (int c = wid; c < NCLS; c += 32) {
        int kc = min(sm.ccnt[c], MAXK);
        if (kc == 0) continue;
        if (kc <= 32) {
            int j1 = (lane < kc) ? sm.clist[c * MAXK + lane] : 0;
            float x1a = sm.sx1[j1], y1a = sm.sy1[j1];
            float x2a = sm.sx2[j1], y2a = sm.sy2[j1], ara = sm.sar[j1];
            unsigned keep =
                __ballot_sync(FULLM, lane < kc && sm.ssc[j1] > CONF_THRESH);
            for (int ii = 0; ii < kc; ii++) {
                if (!((keep >> ii) & 1u)) continue;  // warp-uniform
                float px1 = __shfl_sync(FULLM, x1a, ii);
                float py1 = __shfl_sync(FULLM, y1a, ii);
                float px2 = __shfl_sync(FULLM, x2a, ii);
                float py2 = __shfl_sync(FULLM, y2a, ii);
                float par = __shfl_sync(FULLM, ara, ii);
                float iw = fmaxf(__fsub_rn(fminf(px2, x2a), fmaxf(px1, x1a)), 0.0f);
                float ih = fmaxf(__fsub_rn(fminf(py2, y2a), fmaxf(py1, y1a)), 0.0f);
                float inter = __fmul_rn(iw, ih);
                float den = __fadd_rn(__fsub_rn(__fadd_rn(par, ara), inter), 1e-7f);
                bool s1 = (lane > ii) && (lane < kc) &&
                          (__fdiv_rn(inter, den) > NMS_THRESH);
                keep &= ~__ballot_sync(FULLM, s1);
            }
            if (lane < kc) sm.keepf[j1] = (int)((keep >> lane) & 1u);
        } else {
            int i1 = lane, i2 = lane + 32;
            int j1 = sm.clist[c * MAXK + i1];
            int j2 = (i2 < kc) ? sm.clist[c * MAXK + i2] : 0;
            float x1a = sm.sx1[j1], y1a = sm.sy1[j1];
            float x2a = sm.sx2[j1], y2a = sm.sy2[j1], ara = sm.sar[j1];
            float x1b = sm.sx1[j2], y1b = sm.sy1[j2];
            float x2b = sm.sx2[j2], y2b = sm.sy2[j2], arb = sm.sar[j2];
            unsigned m1 = __ballot_sync(FULLM, sm.ssc[j1] > CONF_THRESH);
            unsigned m2 =
                __ballot_sync(FULLM, i2 < kc && sm.ssc[j2] > CONF_THRESH);
            unsigned long long keep =
                (unsigned long long)m1 | ((unsigned long long)m2 << 32);
            for (int ii = 0; ii < kc; ii++) {
                if (!((keep >> ii) & 1ull)) continue;
                int src = ii & 31;
                bool hi = ii >= 32;
                float px1 = __shfl_sync(FULLM, hi ? x1b : x1a, src);
                float py1 = __shfl_sync(FULLM, hi ? y1b : y1a, src);
                float px2 = __shfl_sync(FULLM, hi ? x2b : x2a, src);
                float py2 = __shfl_sync(FULLM, hi ? y2b : y2a, src);
                float par = __shfl_sync(FULLM, hi ? arb : ara, src);
                float iw1 = fmaxf(__fsub_rn(fminf(px2, x2a), fmaxf(px1, x1a)), 0.0f);
                float ih1 = fmaxf(__fsub_rn(fminf(py2, y2a), fmaxf(py1, y1a)), 0.0f);
                float it1 = __fmul_rn(iw1, ih1);
                float dn1 = __fadd_rn(__fsub_rn(__fadd_rn(par, ara), it1), 1e-7f);
                bool s1 = (i1 > ii) && (__fdiv_rn(it1, dn1) > NMS_THRESH);
                float iw2 = fmaxf(__fsub_rn(fminf(px2, x2b), fmaxf(px1, x1b)), 0.0f);
                float ih2 = fmaxf(__fsub_rn(fminf(py2, y2b), fmaxf(py1, y1b)), 0.0f);
                float it2 = __fmul_rn(iw2, ih2);
                float dn2 = __fadd_rn(__fsub_rn(__fadd_rn(par, arb), it2), 1e-7f);
                bool s2 = (i2 > ii) && (i2 < kc) &&
                          (__fdiv_rn(it2, dn2) > NMS_THRESH);
                unsigned b1 = __ballot_sync(FULLM, s1);
                unsigned b2 = __ballot_sync(FULLM, s2);
                keep &= ~((unsigned long long)b1 |
                          ((unsigned long long)b2 << 32));
            }
            sm.keepf[j1] = (int)((keep >> i1) & 1ull);
            if (i2 < kc) sm.keepf[j2] = (int)((keep >> i2) & 1ull);
        }
    }
    __syncthreads();

    // ---- keep-flag prefix sum (warp shuffles) ----
    int myscan, total;
    {
        int p = sm.keepf[tid];
#pragma unroll
        for (int off = 1; off < 32; off <<= 1) {
            int t = __shfl_up_sync(FULLM, p, off);
            if (lane >= off) p += t;
        }
        if (lane == 31) sm.wscan[wid] = p;
        __syncthreads();
        if (wid == 0) {
            int w = sm.wscan[lane];
            __syncwarp();
#pragma unroll
            for (int off = 1; off < 32; off <<= 1) {
                int t = __shfl_up_sync(FULLM, w, off);
                if (lane >= off) w += t;
            }
            sm.wscan[lane] = w;
        }
        __syncthreads();
        int base = (wid > 0) ? sm.wscan[wid - 1] : 0;
        myscan = base + p;
        total = sm.wscan[31];
    }

    // ---- emit top-300 ----
    float* ob = out;                               // [16][300][4]
    float* os = out + (size_t)BATCH * MAXDET * 4;  // [16][300]
    float* ol = out + (size_t)BATCH * MAXDET * 5;  // [16][300] labels as f32

    if (tid < PRE && sm.keepf[tid]) {
        int m = myscan - 1;
        if (m < MAXDET) {
            float* p = ob + ((size_t)b * MAXDET + m) * 4;
            p[0] = sm.rbx1[tid]; p[1] = sm.rby1[tid];
            p[2] = sm.rbx2[tid]; p[3] = sm.rby2[tid];
            os[b * MAXDET + m] = sm.ssc[tid];
            ol[b * MAXDET + m] = (float)sm.slb[tid];
        }
    }
    for (int m = tid; m < MAXDET; m += 1024) {
        if (m >= total) {
            float* p = ob + ((size_t)b * MAXDET + m) * 4;
            p[0] = 0.0f; p[1] = 0.0f; p[2] = 0.0f; p[3] = 0.0f;
            os[b * MAXDET + m] = 0.0f;
            ol[b * MAXDET + m] = -1.0f;
        }
    }
}

extern "C" void kernel_launch(void* const* d_in, const int* in_sizes, int n_in,
                              void* d_out, int out_size) {
    (void)in_sizes; (void)n_in; (void)out_size;
    const float* preds = (const float*)d_in[0];
    float* out = (float*)d_out;

    cudaFuncSetAttribute(final_kernel,
                         cudaFuncAttributeMaxDynamicSharedMemorySize,
                         (int)sizeof(SMF));

    scan_kernel<<<dim3(ABLK, BATCH), 256>>>(preds);

    cudaLaunchConfig_t cfg = {};
    cfg.gridDim = dim3(BATCH, 1, 1);
    cfg.blockDim = dim3(1024, 1, 1);
    cfg.dynamicSmemBytes = sizeof(SMF);
    cfg.stream = 0;
    cudaLaunchAttribute at[1];
    at[0].id = cudaLaunchAttributeProgrammaticStreamSerialization;
    at[0].val.programmaticStreamSerializationAllowed = 1;
    cfg.attrs = at;
    cfg.numAttrs = 1;
    cudaLaunchKernelEx(&cfg, final_kernel, preds, out);
}